// round 8
// baseline (speedup 1.0000x reference)
#include <cuda_runtime.h>
#include <cuda_bf16.h>
#include <math.h>
#include <stdint.h>

// Problem constants: N=50000, E=800000, dims 128/128/128/64.
#define MAXN 50000
#define MAXE 800000
#define LDW 136     // padded bf16 k-stride for transposed weights
#define LDA 136     // padded bf16 k-stride for smem A tiles
#define SCAN_B 2048
#define PREP_B 64

// ---------------- scratch (device globals) ----------------
__device__ __nv_bfloat16 g_tb[MAXN * 128];  // ping buffer (bf16)
__device__ __nv_bfloat16 g_hb[MAXN * 128];  // pong buffer (bf16)
__device__ float g_h[MAXN * 64];            // layer-3 activations (fp32)
__device__ float g_dis[MAXN];               // rsqrt(deg)
__device__ int   g_deg[MAXN];               // in-degree counts
__device__ int   g_off[MAXN + 1];           // CSR offsets
__device__ int   g_rank[MAXE];              // per-edge rank within dst bucket
__device__ int   g_csrc[MAXE];              // CSR src indices (grouped by dst)
__device__ float g_a[MAXN];                 // attention logits
__device__ float g_red[16384];              // block partials
__device__ float g_scalar[2];               // [0]=gmax, [1]=gsum
__device__ int   g_bsum[64];                // scan block sums
__device__ __nv_bfloat16 g_w1t[128 * LDW];
__device__ __nv_bfloat16 g_w2t[128 * LDW];
__device__ __nv_bfloat16 g_w3t[64 * LDW];

// ---------------- helpers ----------------
__device__ __forceinline__ void mma16816(float* d, uint32_t a0, uint32_t a1,
                                         uint32_t a2, uint32_t a3,
                                         uint32_t b0, uint32_t b1) {
    asm volatile(
        "mma.sync.aligned.m16n8k16.row.col.f32.bf16.bf16.f32 "
        "{%0,%1,%2,%3}, {%4,%5,%6,%7}, {%8,%9}, {%0,%1,%2,%3};"
        : "+f"(d[0]), "+f"(d[1]), "+f"(d[2]), "+f"(d[3])
        : "r"(a0), "r"(a1), "r"(a2), "r"(a3), "r"(b0), "r"(b1));
}

__device__ __forceinline__ float2 bf2f(uint32_t u) {
    return __bfloat1622float2(*reinterpret_cast<__nv_bfloat162*>(&u));
}

// ---------------- fused weight-prep + degree count ----------------
__global__ void prep_count_kernel(const float* __restrict__ W1, const float* __restrict__ W2,
                                  const float* __restrict__ W3,
                                  const int* __restrict__ dst, int e) {
    if (blockIdx.x < PREP_B) {
        int i = blockIdx.x * 256 + threadIdx.x;
        if (i < 128 * 128) {
            int k = i >> 7, nn = i & 127;
            g_w1t[nn * LDW + k] = __float2bfloat16(W1[i]);
            g_w2t[nn * LDW + k] = __float2bfloat16(W2[i]);
        }
        if (i < 128 * 64) {
            int k = i >> 6, nn = i & 63;
            g_w3t[nn * LDW + k] = __float2bfloat16(W3[i]);
        }
    } else {
        int i = (blockIdx.x - PREP_B) * 256 + threadIdx.x;
        if (i < e) g_rank[i] = atomicAdd(&g_deg[dst[i]], 1);
    }
}

// ---------------- scan phase 1: per-block sums ----------------
__global__ void scan1_kernel(int n, int e) {
    __shared__ int sm[256];
    int base = blockIdx.x * SCAN_B + threadIdx.x * 8;
    int s = 0;
#pragma unroll
    for (int i = 0; i < 8; i++) {
        int idx = base + i;
        if (idx < n) s += g_deg[idx];
    }
    sm[threadIdx.x] = s;
    __syncthreads();
    for (int o = 128; o; o >>= 1) {
        if (threadIdx.x < o) sm[threadIdx.x] += sm[threadIdx.x + o];
        __syncthreads();
    }
    if (threadIdx.x == 0) {
        g_bsum[blockIdx.x] = sm[0];
        if (blockIdx.x == 0) g_off[n] = e;
    }
}

// ---------------- scan phase 2: block-local scan + inline block prefix ----------------
__global__ void scan3_kernel(int n) {
    __shared__ int sm[256];
    __shared__ int boff_s;
    int t = threadIdx.x;
    if (t < 32) {
        int v = 0;
        for (int i = t; i < (int)blockIdx.x; i += 32) v += g_bsum[i];
#pragma unroll
        for (int o = 16; o; o >>= 1) v += __shfl_xor_sync(0xFFFFFFFFu, v, o);
        if (t == 0) boff_s = v;
    }
    int base = blockIdx.x * SCAN_B + t * 8;
    int loc[8];
    int s = 0;
#pragma unroll
    for (int i = 0; i < 8; i++) {
        int idx = base + i;
        loc[i] = (idx < n) ? g_deg[idx] : 0;
        s += loc[i];
    }
    sm[t] = s;
    __syncthreads();
    for (int off = 1; off < 256; off <<= 1) {
        int v = (t >= off) ? sm[t - off] : 0;
        __syncthreads();
        sm[t] += v;
        __syncthreads();
    }
    int prefix = boff_s + sm[t] - s;
#pragma unroll
    for (int i = 0; i < 8; i++) {
        int idx = base + i;
        if (idx < n) {
            g_off[idx] = prefix;
            prefix += loc[i];
            g_dis[idx] = rsqrtf((float)loc[i] + 1.0f);
        }
    }
}

// ---------------- merged layer-1 GEMM + CSR fill ----------------
// blocks [0, ng): GEMM1 (x fp32 @ W1 -> T bf16). blocks [ng, ...): CSR fill.
__global__ __launch_bounds__(256) void gemm1_fill_kernel(const float* __restrict__ A,
                                                         const __nv_bfloat16* __restrict__ Wt,
                                                         __nv_bfloat16* __restrict__ T,
                                                         const int* __restrict__ src,
                                                         const int* __restrict__ dst,
                                                         int n, int e, int ng) {
    if (blockIdx.x >= ng) {
        int i = (blockIdx.x - ng) * 256 + threadIdx.x;
        if (i < e) g_csrc[g_off[dst[i]] + g_rank[i]] = src[i];
        return;
    }
    extern __shared__ __nv_bfloat16 sw[];  // [128][LDW]
    int t = threadIdx.x;
    for (int i = t; i < 128 * LDW / 8; i += 256)
        reinterpret_cast<uint4*>(sw)[i] = reinterpret_cast<const uint4*>(Wt)[i];
    __syncthreads();

    int warp = t >> 5, lane = t & 31;
    int g = lane >> 2, tg = lane & 3;
    int row0 = blockIdx.x * 128 + warp * 16 + g;
    int row1 = row0 + 8;
    bool v0 = row0 < n, v1 = row1 < n;

    float acc[16][4];
#pragma unroll
    for (int i = 0; i < 16; i++)
#pragma unroll
        for (int j = 0; j < 4; j++) acc[i][j] = 0.f;

    const float* A0 = A + (size_t)row0 * 128;
    const float* A1 = A + (size_t)row1 * 128;

#pragma unroll
    for (int ks = 0; ks < 8; ks++) {
        int k0 = ks * 16 + tg * 2;
        float2 z = make_float2(0.f, 0.f);
        float2 x0 = v0 ? *reinterpret_cast<const float2*>(A0 + k0) : z;
        float2 x1 = v1 ? *reinterpret_cast<const float2*>(A1 + k0) : z;
        float2 x2 = v0 ? *reinterpret_cast<const float2*>(A0 + k0 + 8) : z;
        float2 x3 = v1 ? *reinterpret_cast<const float2*>(A1 + k0 + 8) : z;
        __nv_bfloat162 h0 = __float22bfloat162_rn(x0);
        __nv_bfloat162 h1 = __float22bfloat162_rn(x1);
        __nv_bfloat162 h2 = __float22bfloat162_rn(x2);
        __nv_bfloat162 h3 = __float22bfloat162_rn(x3);
        uint32_t a0 = *reinterpret_cast<uint32_t*>(&h0);
        uint32_t a1 = *reinterpret_cast<uint32_t*>(&h1);
        uint32_t a2 = *reinterpret_cast<uint32_t*>(&h2);
        uint32_t a3 = *reinterpret_cast<uint32_t*>(&h3);

        const __nv_bfloat16* wh = sw + g * LDW + ks * 16 + tg * 2;
#pragma unroll
        for (int nt = 0; nt < 16; nt++) {
            uint32_t b0 = *reinterpret_cast<const uint32_t*>(wh + nt * 8 * LDW);
            uint32_t b1 = *reinterpret_cast<const uint32_t*>(wh + nt * 8 * LDW + 8);
            mma16816(acc[nt], a0, a1, a2, a3, b0, b1);
        }
    }

#pragma unroll
    for (int nt = 0; nt < 16; nt++) {
        int col = nt * 8 + tg * 2;
        if (v0) {
            __nv_bfloat162 o = __float22bfloat162_rn(make_float2(acc[nt][0], acc[nt][1]));
            *reinterpret_cast<__nv_bfloat162*>(&T[(size_t)row0 * 128 + col]) = o;
        }
        if (v1) {
            __nv_bfloat162 o = __float22bfloat162_rn(make_float2(acc[nt][2], acc[nt][3]));
            *reinterpret_cast<__nv_bfloat162*>(&T[(size_t)row1 * 128 + col]) = o;
        }
    }
}

// ---------------- fused aggregation + GEMM ----------------
// agg (warp-per-node, 16 nodes/warp, unroll x8) over T_prev[*,128] -> relu(bias+..)
// staged bf16 in SMEM, then MMA vs Wt[OUT][LDW] -> Tout[*,OUT].
template <int OUT>
__global__ __launch_bounds__(256) void agg_gemm_kernel(const __nv_bfloat16* __restrict__ T,
                                                       const float* __restrict__ bias,
                                                       const __nv_bfloat16* __restrict__ Wt,
                                                       __nv_bfloat16* __restrict__ Tout, int n) {
    extern __shared__ __nv_bfloat16 smem[];
    __nv_bfloat16* sw = smem;               // [OUT][LDW]
    __nv_bfloat16* Asm = smem + OUT * LDW;  // [128][LDA]
    int t = threadIdx.x, warp = t >> 5, lane = t & 31;

    constexpr int NU4 = OUT * LDW / 8;
    for (int i = t; i < NU4; i += 256)
        reinterpret_cast<uint4*>(sw)[i] = reinterpret_cast<const uint4*>(Wt)[i];

    int base = blockIdx.x * 128;
    float bb[4] = {bias[lane * 4], bias[lane * 4 + 1], bias[lane * 4 + 2], bias[lane * 4 + 3]};

    // ---- agg phase: each warp aggregates its own 16 rows ----
    for (int rr = 0; rr < 16; rr++) {
        int r = warp * 16 + rr;
        int node = base + r;
        float acc0 = 0.f, acc1 = 0.f, acc2 = 0.f, acc3 = 0.f;
        if (node < n) {
            float dn = g_dis[node];
            float w0 = dn * dn;
            {
                uint2 u = *reinterpret_cast<const uint2*>(&T[(size_t)node * 128 + lane * 4]);
                float2 f0 = bf2f(u.x), f1 = bf2f(u.y);
                acc0 = f0.x * w0; acc1 = f0.y * w0;
                acc2 = f1.x * w0; acc3 = f1.y * w0;
            }
            int p0 = g_off[node];
            int cnt = g_off[node + 1] - p0;
            int sv = (lane < cnt) ? g_csrc[p0 + lane] : 0;
            int j = 0;
            for (; j + 8 <= cnt; j += 8) {
                if ((j & 31) == 0 && j)
                    sv = (j + lane < cnt) ? g_csrc[p0 + j + lane] : 0;
                int jb = j & 31;
                int s[8];
#pragma unroll
                for (int q = 0; q < 8; q++) s[q] = __shfl_sync(0xFFFFFFFFu, sv, jb + q);
                float w[8];
#pragma unroll
                for (int q = 0; q < 8; q++) w[q] = g_dis[s[q]] * dn;
                uint2 u[8];
#pragma unroll
                for (int q = 0; q < 8; q++)
                    u[q] = *reinterpret_cast<const uint2*>(&T[(size_t)s[q] * 128 + lane * 4]);
#pragma unroll
                for (int q = 0; q < 8; q++) {
                    float2 f0 = bf2f(u[q].x), f1 = bf2f(u[q].y);
                    acc0 = fmaf(f0.x, w[q], acc0); acc1 = fmaf(f0.y, w[q], acc1);
                    acc2 = fmaf(f1.x, w[q], acc2); acc3 = fmaf(f1.y, w[q], acc3);
                }
            }
            for (; j < cnt; j++) {
                if ((j & 31) == 0 && j)
                    sv = (j + lane < cnt) ? g_csrc[p0 + j + lane] : 0;
                int s = __shfl_sync(0xFFFFFFFFu, sv, j & 31);
                float w = g_dis[s] * dn;
                uint2 u = *reinterpret_cast<const uint2*>(&T[(size_t)s * 128 + lane * 4]);
                float2 f0 = bf2f(u.x), f1 = bf2f(u.y);
                acc0 = fmaf(f0.x, w, acc0); acc1 = fmaf(f0.y, w, acc1);
                acc2 = fmaf(f1.x, w, acc2); acc3 = fmaf(f1.y, w, acc3);
            }
            acc0 = fmaxf(acc0 + bb[0], 0.f);
            acc1 = fmaxf(acc1 + bb[1], 0.f);
            acc2 = fmaxf(acc2 + bb[2], 0.f);
            acc3 = fmaxf(acc3 + bb[3], 0.f);
        }
        __nv_bfloat162 o0 = __float22bfloat162_rn(make_float2(acc0, acc1));
        __nv_bfloat162 o1 = __float22bfloat162_rn(make_float2(acc2, acc3));
        uint2 up;
        up.x = *reinterpret_cast<uint32_t*>(&o0);
        up.y = *reinterpret_cast<uint32_t*>(&o1);
        *reinterpret_cast<uint2*>(&Asm[(size_t)r * LDA + lane * 4]) = up;
    }
    __syncthreads();

    // ---- GEMM phase: A from SMEM ----
    int g = lane >> 2, tg = lane & 3;
    int r0 = warp * 16 + g;
    constexpr int NT = OUT / 8;
    float acc[NT][4];
#pragma unroll
    for (int i = 0; i < NT; i++)
#pragma unroll
        for (int j = 0; j < 4; j++) acc[i][j] = 0.f;

#pragma unroll
    for (int ks = 0; ks < 8; ks++) {
        int k0 = ks * 16 + tg * 2;
        uint32_t a0 = *reinterpret_cast<const uint32_t*>(&Asm[r0 * LDA + k0]);
        uint32_t a1 = *reinterpret_cast<const uint32_t*>(&Asm[(r0 + 8) * LDA + k0]);
        uint32_t a2 = *reinterpret_cast<const uint32_t*>(&Asm[r0 * LDA + k0 + 8]);
        uint32_t a3 = *reinterpret_cast<const uint32_t*>(&Asm[(r0 + 8) * LDA + k0 + 8]);
        const __nv_bfloat16* wh = sw + g * LDW + ks * 16 + tg * 2;
#pragma unroll
        for (int nt = 0; nt < NT; nt++) {
            uint32_t b0 = *reinterpret_cast<const uint32_t*>(wh + nt * 8 * LDW);
            uint32_t b1 = *reinterpret_cast<const uint32_t*>(wh + nt * 8 * LDW + 8);
            mma16816(acc[nt], a0, a1, a2, a3, b0, b1);
        }
    }

    int row0 = base + r0, row1 = row0 + 8;
#pragma unroll
    for (int nt = 0; nt < NT; nt++) {
        int col = nt * 8 + tg * 2;
        if (row0 < n) {
            __nv_bfloat162 o = __float22bfloat162_rn(make_float2(acc[nt][0], acc[nt][1]));
            *reinterpret_cast<__nv_bfloat162*>(&Tout[(size_t)row0 * OUT + col]) = o;
        }
        if (row1 < n) {
            __nv_bfloat162 o = __float22bfloat162_rn(make_float2(acc[nt][2], acc[nt][3]));
            *reinterpret_cast<__nv_bfloat162*>(&Tout[(size_t)row1 * OUT + col]) = o;
        }
    }
}

// ---------------- fused layer-3 agg + attention score (OUT=64, unroll x8) ----------------
__global__ __launch_bounds__(256) void agg3_attn_kernel(const __nv_bfloat16* __restrict__ T,
                                                        const float* __restrict__ bias,
                                                        const float* __restrict__ aW,
                                                        const float* __restrict__ ab,
                                                        float* __restrict__ H, int n) {
    int warp = (blockIdx.x * blockDim.x + threadIdx.x) >> 5;
    int lane = threadIdx.x & 31;
    float a = -INFINITY;

    if (warp < n) {
        float dn = g_dis[warp];
        float w0 = dn * dn;
        float acc0, acc1;
        {
            uint32_t u = *reinterpret_cast<const uint32_t*>(&T[(size_t)warp * 64 + lane * 2]);
            float2 f = bf2f(u);
            acc0 = f.x * w0; acc1 = f.y * w0;
        }
        int p0 = g_off[warp];
        int cnt = g_off[warp + 1] - p0;
        int sv = (lane < cnt) ? g_csrc[p0 + lane] : 0;
        int j = 0;
        for (; j + 8 <= cnt; j += 8) {
            if ((j & 31) == 0 && j)
                sv = (j + lane < cnt) ? g_csrc[p0 + j + lane] : 0;
            int jb = j & 31;
            int s[8];
#pragma unroll
            for (int q = 0; q < 8; q++) s[q] = __shfl_sync(0xFFFFFFFFu, sv, jb + q);
            float w[8];
#pragma unroll
            for (int q = 0; q < 8; q++) w[q] = g_dis[s[q]] * dn;
            uint32_t u[8];
#pragma unroll
            for (int q = 0; q < 8; q++)
                u[q] = *reinterpret_cast<const uint32_t*>(&T[(size_t)s[q] * 64 + lane * 2]);
#pragma unroll
            for (int q = 0; q < 8; q++) {
                float2 f = bf2f(u[q]);
                acc0 = fmaf(f.x, w[q], acc0); acc1 = fmaf(f.y, w[q], acc1);
            }
        }
        for (; j < cnt; j++) {
            if ((j & 31) == 0 && j)
                sv = (j + lane < cnt) ? g_csrc[p0 + j + lane] : 0;
            int s = __shfl_sync(0xFFFFFFFFu, sv, j & 31);
            float w = g_dis[s] * dn;
            uint32_t u = *reinterpret_cast<const uint32_t*>(&T[(size_t)s * 64 + lane * 2]);
            float2 f = bf2f(u);
            acc0 = fmaf(f.x, w, acc0); acc1 = fmaf(f.y, w, acc1);
        }

        float v0 = acc0 + bias[lane * 2];
        float v1 = acc1 + bias[lane * 2 + 1];
        v0 = v0 > 0.f ? v0 : 0.f;
        v1 = v1 > 0.f ? v1 : 0.f;
        *reinterpret_cast<float2*>(&H[(size_t)warp * 64 + lane * 2]) = make_float2(v0, v1);

        float part = v0 * aW[lane * 2] + v1 * aW[lane * 2 + 1];
#pragma unroll
        for (int o = 16; o; o >>= 1) part += __shfl_xor_sync(0xFFFFFFFFu, part, o);
        a = part + ab[0];
        if (lane == 0) g_a[warp] = a;
    }

    __shared__ float sm[8];
    __shared__ float bmax_s;
    if (lane == 0) sm[threadIdx.x >> 5] = a;
    __syncthreads();
    if (threadIdx.x == 0) {
        float m = sm[0];
#pragma unroll
        for (int i = 1; i < 8; i++) m = fmaxf(m, sm[i]);
        bmax_s = m;
    }
    __syncthreads();
    float bmax = bmax_s;
    float es = (lane == 0 && warp < n) ? expf(a - bmax) : 0.f;
    if (lane == 0) sm[threadIdx.x >> 5] = es;
    __syncthreads();
    if (threadIdx.x == 0) {
        float s = sm[0];
#pragma unroll
        for (int i = 1; i < 8; i++) s += sm[i];
        g_red[blockIdx.x * 2] = bmax;
        g_red[blockIdx.x * 2 + 1] = s;
    }
}

// ---------------- softmax combine + final ----------------
__global__ void combine_kernel(int nb) {
    __shared__ float sm[1024];
    int t = threadIdx.x;
    float m = -INFINITY;
    for (int i = t; i < nb; i += 1024) m = fmaxf(m, g_red[i * 2]);
    sm[t] = m;
    __syncthreads();
    for (int o = 512; o; o >>= 1) {
        if (t < o) sm[t] = fmaxf(sm[t], sm[t + o]);
        __syncthreads();
    }
    float gmax = sm[0];
    __syncthreads();
    float s = 0.f;
    for (int i = t; i < nb; i += 1024) s += g_red[i * 2 + 1] * expf(g_red[i * 2] - gmax);
    sm[t] = s;
    __syncthreads();
    for (int o = 512; o; o >>= 1) {
        if (t < o) sm[t] += sm[t + o];
        __syncthreads();
    }
    if (t == 0) { g_scalar[0] = gmax; g_scalar[1] = sm[0]; }
}

__global__ void final_kernel(const float* __restrict__ H,
                             const float* __restrict__ fW,
                             const float* __restrict__ fb,
                             float* __restrict__ out, int n) {
    int gw = (blockIdx.x * blockDim.x + threadIdx.x) >> 5;
    int lane = threadIdx.x & 31;
    if (gw >= n) return;
    float v = H[(size_t)gw * 64 + lane] * fW[lane] +
              H[(size_t)gw * 64 + lane + 32] * fW[lane + 32];
#pragma unroll
    for (int o = 16; o; o >>= 1) v += __shfl_xor_sync(0xFFFFFFFFu, v, o);
    if (lane == 0) {
        float attn = expf(g_a[gw] - g_scalar[0]) / g_scalar[1];
        float z = attn * v + fb[0];
        out[gw] = 1.f / (1.f + expf(-z));
        out[n + gw] = attn;
    }
}

// ---------------- launch ----------------
extern "C" void kernel_launch(void* const* d_in, const int* in_sizes, int n_in,
                              void* d_out, int out_size) {
    const float* x   = (const float*)d_in[0];
    const int*   ei  = (const int*)d_in[1];
    const float* W1  = (const float*)d_in[2];
    const float* b1  = (const float*)d_in[3];
    const float* W2  = (const float*)d_in[4];
    const float* b2  = (const float*)d_in[5];
    const float* W3  = (const float*)d_in[6];
    const float* b3  = (const float*)d_in[7];
    const float* aW  = (const float*)d_in[8];
    const float* ab  = (const float*)d_in[9];
    const float* fW  = (const float*)d_in[10];
    const float* fb  = (const float*)d_in[11];
    float* out = (float*)d_out;

    int N = in_sizes[0] / 128;
    int E = in_sizes[1] / 2;
    const int* src = ei;
    const int* dst = ei + E;

    __nv_bfloat16 *tb, *hb, *w1t, *w2t, *w3t;
    float* h3;
    int* deg_ptr;
    cudaGetSymbolAddress((void**)&tb, g_tb);
    cudaGetSymbolAddress((void**)&hb, g_hb);
    cudaGetSymbolAddress((void**)&h3, g_h);
    cudaGetSymbolAddress((void**)&deg_ptr, g_deg);
    cudaGetSymbolAddress((void**)&w1t, g_w1t);
    cudaGetSymbolAddress((void**)&w2t, g_w2t);
    cudaGetSymbolAddress((void**)&w3t, g_w3t);

    const int SM1   = 128 * LDW * 2;                    // 34816
    const int AG128 = 128 * LDW * 2 + 128 * LDA * 2;    // 69632
    const int AG64  = 64 * LDW * 2 + 128 * LDA * 2;     // 52224
    cudaFuncSetAttribute((const void*)gemm1_fill_kernel,
                         cudaFuncAttributeMaxDynamicSharedMemorySize, SM1);
    cudaFuncSetAttribute((const void*)agg_gemm_kernel<128>,
                         cudaFuncAttributeMaxDynamicSharedMemorySize, AG128);
    cudaFuncSetAttribute((const void*)agg_gemm_kernel<64>,
                         cudaFuncAttributeMaxDynamicSharedMemorySize, AG64);

    cudaMemsetAsync(deg_ptr, 0, (size_t)N * sizeof(int));
    prep_count_kernel<<<PREP_B + (E + 255) / 256, 256>>>(W1, W2, W3, dst, E);
    int nb = (N + SCAN_B - 1) / SCAN_B;
    scan1_kernel<<<nb, 256>>>(N, E);
    scan3_kernel<<<nb, 256>>>(N);

    int warpGrid = (N * 32 + 255) / 256;
    int mmaGrid = (N + 127) / 128;

    // layer 1 GEMM overlapped with CSR fill
    gemm1_fill_kernel<<<mmaGrid + (E + 255) / 256, 256, SM1>>>(x, w1t, tb, src, dst, N, E, mmaGrid);
    // fused agg1 + GEMM2 (tb -> hb), agg2 + GEMM3 (hb -> tb)
    agg_gemm_kernel<128><<<mmaGrid, 256, AG128>>>(tb, b1, w2t, hb, N);
    agg_gemm_kernel<64><<<mmaGrid, 256, AG64>>>(hb, b2, w3t, tb, N);
    // agg3 + attention logits/partials
    agg3_attn_kernel<<<warpGrid, 256>>>(tb, b3, aW, ab, h3, N);

    combine_kernel<<<1, 1024>>>(warpGrid);
    final_kernel<<<warpGrid, 256>>>(h3, fW, fb, out, N);
}

// round 9
// speedup vs baseline: 1.0626x; 1.0626x over previous
#include <cuda_runtime.h>
#include <cuda_bf16.h>
#include <math.h>
#include <stdint.h>

// Problem constants: N=50000, E=800000, dims 128/128/128/64.
#define MAXN 50000
#define MAXE 800000
#define LDW 136     // padded bf16 k-stride for transposed weights
#define SCAN_B 2048
#define PREP_B 64

// ---------------- scratch (device globals) ----------------
__device__ __nv_bfloat16 g_tb[MAXN * 128];  // GEMM output (bf16)
__device__ __nv_bfloat16 g_hb[MAXN * 128];  // layer activations (bf16)
__device__ float g_h[MAXN * 64];            // layer-3 activations (fp32)
__device__ float g_dis[MAXN];               // rsqrt(deg)
__device__ int   g_deg[MAXN];               // in-degree counts
__device__ int   g_off[MAXN + 1];           // CSR offsets
__device__ int   g_rank[MAXE];              // per-edge rank within dst bucket
__device__ int   g_csrc[MAXE];              // CSR src indices (grouped by dst)
__device__ float g_a[MAXN];                 // attention logits
__device__ float g_red[16384];              // block partials
__device__ float g_scalar[2];               // [0]=gmax, [1]=gsum
__device__ int   g_bsum[64];                // scan block sums
__device__ __nv_bfloat16 g_w1t[128 * LDW];
__device__ __nv_bfloat16 g_w2t[128 * LDW];
__device__ __nv_bfloat16 g_w3t[64 * LDW];

// ---------------- helpers ----------------
__device__ __forceinline__ void mma16816(float* d, uint32_t a0, uint32_t a1,
                                         uint32_t a2, uint32_t a3,
                                         uint32_t b0, uint32_t b1) {
    asm volatile(
        "mma.sync.aligned.m16n8k16.row.col.f32.bf16.bf16.f32 "
        "{%0,%1,%2,%3}, {%4,%5,%6,%7}, {%8,%9}, {%0,%1,%2,%3};"
        : "+f"(d[0]), "+f"(d[1]), "+f"(d[2]), "+f"(d[3])
        : "r"(a0), "r"(a1), "r"(a2), "r"(a3), "r"(b0), "r"(b1));
}

__device__ __forceinline__ float2 bf2f(uint32_t u) {
    return __bfloat1622float2(*reinterpret_cast<__nv_bfloat162*>(&u));
}

// ---------------- fused weight-prep + degree count ----------------
__global__ void prep_count_kernel(const float* __restrict__ W1, const float* __restrict__ W2,
                                  const float* __restrict__ W3,
                                  const int* __restrict__ dst, int e) {
    if (blockIdx.x < PREP_B) {
        int i = blockIdx.x * 256 + threadIdx.x;
        if (i < 128 * 128) {
            int k = i >> 7, nn = i & 127;
            g_w1t[nn * LDW + k] = __float2bfloat16(W1[i]);
            g_w2t[nn * LDW + k] = __float2bfloat16(W2[i]);
        }
        if (i < 128 * 64) {
            int k = i >> 6, nn = i & 63;
            g_w3t[nn * LDW + k] = __float2bfloat16(W3[i]);
        }
    } else {
        int i = (blockIdx.x - PREP_B) * 256 + threadIdx.x;
        if (i < e) g_rank[i] = atomicAdd(&g_deg[dst[i]], 1);
    }
}

// ---------------- scan phase 1: per-block sums ----------------
__global__ void scan1_kernel(int n, int e) {
    __shared__ int sm[256];
    int base = blockIdx.x * SCAN_B + threadIdx.x * 8;
    int s = 0;
#pragma unroll
    for (int i = 0; i < 8; i++) {
        int idx = base + i;
        if (idx < n) s += g_deg[idx];
    }
    sm[threadIdx.x] = s;
    __syncthreads();
    for (int o = 128; o; o >>= 1) {
        if (threadIdx.x < o) sm[threadIdx.x] += sm[threadIdx.x + o];
        __syncthreads();
    }
    if (threadIdx.x == 0) {
        g_bsum[blockIdx.x] = sm[0];
        if (blockIdx.x == 0) g_off[n] = e;
    }
}

// ---------------- scan phase 2: block-local scan + inline block prefix ----------------
__global__ void scan3_kernel(int n) {
    __shared__ int sm[256];
    __shared__ int boff_s;
    int t = threadIdx.x;
    if (t < 32) {
        int v = 0;
        for (int i = t; i < (int)blockIdx.x; i += 32) v += g_bsum[i];
#pragma unroll
        for (int o = 16; o; o >>= 1) v += __shfl_xor_sync(0xFFFFFFFFu, v, o);
        if (t == 0) boff_s = v;
    }
    int base = blockIdx.x * SCAN_B + t * 8;
    int loc[8];
    int s = 0;
#pragma unroll
    for (int i = 0; i < 8; i++) {
        int idx = base + i;
        loc[i] = (idx < n) ? g_deg[idx] : 0;
        s += loc[i];
    }
    sm[t] = s;
    __syncthreads();
    for (int off = 1; off < 256; off <<= 1) {
        int v = (t >= off) ? sm[t - off] : 0;
        __syncthreads();
        sm[t] += v;
        __syncthreads();
    }
    int prefix = boff_s + sm[t] - s;
#pragma unroll
    for (int i = 0; i < 8; i++) {
        int idx = base + i;
        if (idx < n) {
            g_off[idx] = prefix;
            prefix += loc[i];
            g_dis[idx] = rsqrtf((float)loc[i] + 1.0f);
        }
    }
}

__global__ void fill_kernel(const int* __restrict__ src, const int* __restrict__ dst, int e) {
    int i = blockIdx.x * blockDim.x + threadIdx.x;
    if (i >= e) return;
    g_csrc[g_off[dst[i]] + g_rank[i]] = src[i];
}

// ---------------- bf16 mma GEMM: T[n,OUT](bf16) = A[n,128] @ W[128,OUT] ----------------
template <int OUT, typename AF>
__global__ __launch_bounds__(256) void mma_gemm_kernel(const AF* __restrict__ A,
                                                       const __nv_bfloat16* __restrict__ Wt,
                                                       __nv_bfloat16* __restrict__ T, int n) {
    extern __shared__ __nv_bfloat16 sw[];  // [OUT][LDW]
    int t = threadIdx.x;
    constexpr int NU4 = OUT * LDW / 8;
    for (int i = t; i < NU4; i += 256)
        reinterpret_cast<uint4*>(sw)[i] = reinterpret_cast<const uint4*>(Wt)[i];
    __syncthreads();

    int warp = t >> 5, lane = t & 31;
    int g = lane >> 2, tg = lane & 3;
    int row0 = blockIdx.x * 128 + warp * 16 + g;
    int row1 = row0 + 8;
    bool v0 = row0 < n, v1 = row1 < n;

    constexpr int NT = OUT / 8;
    float acc[NT][4];
#pragma unroll
    for (int i = 0; i < NT; i++)
#pragma unroll
        for (int j = 0; j < 4; j++) acc[i][j] = 0.f;

    const AF* A0 = A + (size_t)row0 * 128;
    const AF* A1 = A + (size_t)row1 * 128;

#pragma unroll
    for (int ks = 0; ks < 8; ks++) {
        int k0 = ks * 16 + tg * 2;
        uint32_t a0, a1, a2, a3;
        if (sizeof(AF) == 4) {
            const float* F0 = (const float*)A0;
            const float* F1 = (const float*)A1;
            float2 z = make_float2(0.f, 0.f);
            float2 x0 = v0 ? *reinterpret_cast<const float2*>(F0 + k0) : z;
            float2 x1 = v1 ? *reinterpret_cast<const float2*>(F1 + k0) : z;
            float2 x2 = v0 ? *reinterpret_cast<const float2*>(F0 + k0 + 8) : z;
            float2 x3 = v1 ? *reinterpret_cast<const float2*>(F1 + k0 + 8) : z;
            __nv_bfloat162 h0 = __float22bfloat162_rn(x0);
            __nv_bfloat162 h1 = __float22bfloat162_rn(x1);
            __nv_bfloat162 h2 = __float22bfloat162_rn(x2);
            __nv_bfloat162 h3 = __float22bfloat162_rn(x3);
            a0 = *reinterpret_cast<uint32_t*>(&h0);
            a1 = *reinterpret_cast<uint32_t*>(&h1);
            a2 = *reinterpret_cast<uint32_t*>(&h2);
            a3 = *reinterpret_cast<uint32_t*>(&h3);
        } else {
            const __nv_bfloat16* B0 = (const __nv_bfloat16*)A0;
            const __nv_bfloat16* B1 = (const __nv_bfloat16*)A1;
            a0 = v0 ? *reinterpret_cast<const uint32_t*>(B0 + k0) : 0u;
            a1 = v1 ? *reinterpret_cast<const uint32_t*>(B1 + k0) : 0u;
            a2 = v0 ? *reinterpret_cast<const uint32_t*>(B0 + k0 + 8) : 0u;
            a3 = v1 ? *reinterpret_cast<const uint32_t*>(B1 + k0 + 8) : 0u;
        }

        const __nv_bfloat16* wh = sw + g * LDW + ks * 16 + tg * 2;
#pragma unroll
        for (int nt = 0; nt < NT; nt++) {
            uint32_t b0 = *reinterpret_cast<const uint32_t*>(wh + nt * 8 * LDW);
            uint32_t b1 = *reinterpret_cast<const uint32_t*>(wh + nt * 8 * LDW + 8);
            mma16816(acc[nt], a0, a1, a2, a3, b0, b1);
        }
    }

#pragma unroll
    for (int nt = 0; nt < NT; nt++) {
        int col = nt * 8 + tg * 2;
        if (v0) {
            __nv_bfloat162 o = __float22bfloat162_rn(make_float2(acc[nt][0], acc[nt][1]));
            *reinterpret_cast<__nv_bfloat162*>(&T[(size_t)row0 * OUT + col]) = o;
        }
        if (v1) {
            __nv_bfloat162 o = __float22bfloat162_rn(make_float2(acc[nt][2], acc[nt][3]));
            *reinterpret_cast<__nv_bfloat162*>(&T[(size_t)row1 * OUT + col]) = o;
        }
    }
}

// ---------------- aggregation layers 1,2 (bf16->bf16, OUT=128, unroll x8) ----------------
// dis values batch-gathered once per 32 edges and broadcast via shfl (LSU relief).
__global__ __launch_bounds__(256) void agg128_kernel(const __nv_bfloat16* __restrict__ T,
                                                     const float* __restrict__ bias,
                                                     __nv_bfloat16* __restrict__ H, int n) {
    int warp = (blockIdx.x * blockDim.x + threadIdx.x) >> 5;
    int lane = threadIdx.x & 31;
    if (warp >= n) return;

    float dn = g_dis[warp];
    float w0 = dn * dn;
    float acc[4];
    {
        uint2 u = *reinterpret_cast<const uint2*>(&T[(size_t)warp * 128 + lane * 4]);
        float2 f0 = bf2f(u.x), f1 = bf2f(u.y);
        acc[0] = f0.x * w0; acc[1] = f0.y * w0;
        acc[2] = f1.x * w0; acc[3] = f1.y * w0;
    }

    int p0 = g_off[warp];
    int cnt = g_off[warp + 1] - p0;
    int sv = 0;
    float wv = 0.f;
    if (lane < cnt) { sv = g_csrc[p0 + lane]; wv = g_dis[sv]; }
    int j = 0;
    for (; j + 8 <= cnt; j += 8) {
        if ((j & 31) == 0 && j) {
            sv = 0; wv = 0.f;
            if (j + lane < cnt) { sv = g_csrc[p0 + j + lane]; wv = g_dis[sv]; }
        }
        int jb = j & 31;
        int s[8];
        float w[8];
#pragma unroll
        for (int q = 0; q < 8; q++) {
            s[q] = __shfl_sync(0xFFFFFFFFu, sv, jb + q);
            w[q] = __shfl_sync(0xFFFFFFFFu, wv, jb + q) * dn;
        }
        uint2 u[8];
#pragma unroll
        for (int q = 0; q < 8; q++)
            u[q] = *reinterpret_cast<const uint2*>(&T[(size_t)s[q] * 128 + lane * 4]);
#pragma unroll
        for (int q = 0; q < 8; q++) {
            float2 f0 = bf2f(u[q].x), f1 = bf2f(u[q].y);
            acc[0] = fmaf(f0.x, w[q], acc[0]); acc[1] = fmaf(f0.y, w[q], acc[1]);
            acc[2] = fmaf(f1.x, w[q], acc[2]); acc[3] = fmaf(f1.y, w[q], acc[3]);
        }
    }
    for (; j < cnt; j++) {
        if ((j & 31) == 0 && j) {
            sv = 0; wv = 0.f;
            if (j + lane < cnt) { sv = g_csrc[p0 + j + lane]; wv = g_dis[sv]; }
        }
        int s = __shfl_sync(0xFFFFFFFFu, sv, j & 31);
        float w = __shfl_sync(0xFFFFFFFFu, wv, j & 31) * dn;
        uint2 u = *reinterpret_cast<const uint2*>(&T[(size_t)s * 128 + lane * 4]);
        float2 f0 = bf2f(u.x), f1 = bf2f(u.y);
        acc[0] = fmaf(f0.x, w, acc[0]); acc[1] = fmaf(f0.y, w, acc[1]);
        acc[2] = fmaf(f1.x, w, acc[2]); acc[3] = fmaf(f1.y, w, acc[3]);
    }

#pragma unroll
    for (int q = 0; q < 4; q++) {
        float v = acc[q] + bias[lane * 4 + q];
        acc[q] = v > 0.f ? v : 0.f;
    }
    __nv_bfloat162 o0 = __float22bfloat162_rn(make_float2(acc[0], acc[1]));
    __nv_bfloat162 o1 = __float22bfloat162_rn(make_float2(acc[2], acc[3]));
    uint2 u;
    u.x = *reinterpret_cast<uint32_t*>(&o0);
    u.y = *reinterpret_cast<uint32_t*>(&o1);
    *reinterpret_cast<uint2*>(&H[(size_t)warp * 128 + lane * 4]) = u;
}

// ---------------- fused layer-3 agg + attention score (OUT=64, unroll x8) ----------------
__global__ __launch_bounds__(256) void agg3_attn_kernel(const __nv_bfloat16* __restrict__ T,
                                                        const float* __restrict__ bias,
                                                        const float* __restrict__ aW,
                                                        const float* __restrict__ ab,
                                                        float* __restrict__ H, int n) {
    int warp = (blockIdx.x * blockDim.x + threadIdx.x) >> 5;
    int lane = threadIdx.x & 31;
    float a = -INFINITY;

    if (warp < n) {
        float dn = g_dis[warp];
        float w0 = dn * dn;
        float acc0, acc1;
        {
            uint32_t u = *reinterpret_cast<const uint32_t*>(&T[(size_t)warp * 64 + lane * 2]);
            float2 f = bf2f(u);
            acc0 = f.x * w0; acc1 = f.y * w0;
        }
        int p0 = g_off[warp];
        int cnt = g_off[warp + 1] - p0;
        int sv = 0;
        float wv = 0.f;
        if (lane < cnt) { sv = g_csrc[p0 + lane]; wv = g_dis[sv]; }
        int j = 0;
        for (; j + 8 <= cnt; j += 8) {
            if ((j & 31) == 0 && j) {
                sv = 0; wv = 0.f;
                if (j + lane < cnt) { sv = g_csrc[p0 + j + lane]; wv = g_dis[sv]; }
            }
            int jb = j & 31;
            int s[8];
            float w[8];
#pragma unroll
            for (int q = 0; q < 8; q++) {
                s[q] = __shfl_sync(0xFFFFFFFFu, sv, jb + q);
                w[q] = __shfl_sync(0xFFFFFFFFu, wv, jb + q) * dn;
            }
            uint32_t u[8];
#pragma unroll
            for (int q = 0; q < 8; q++)
                u[q] = *reinterpret_cast<const uint32_t*>(&T[(size_t)s[q] * 64 + lane * 2]);
#pragma unroll
            for (int q = 0; q < 8; q++) {
                float2 f = bf2f(u[q]);
                acc0 = fmaf(f.x, w[q], acc0); acc1 = fmaf(f.y, w[q], acc1);
            }
        }
        for (; j < cnt; j++) {
            if ((j & 31) == 0 && j) {
                sv = 0; wv = 0.f;
                if (j + lane < cnt) { sv = g_csrc[p0 + j + lane]; wv = g_dis[sv]; }
            }
            int s = __shfl_sync(0xFFFFFFFFu, sv, j & 31);
            float w = __shfl_sync(0xFFFFFFFFu, wv, j & 31) * dn;
            uint32_t u = *reinterpret_cast<const uint32_t*>(&T[(size_t)s * 64 + lane * 2]);
            float2 f = bf2f(u);
            acc0 = fmaf(f.x, w, acc0); acc1 = fmaf(f.y, w, acc1);
        }

        float v0 = acc0 + bias[lane * 2];
        float v1 = acc1 + bias[lane * 2 + 1];
        v0 = v0 > 0.f ? v0 : 0.f;
        v1 = v1 > 0.f ? v1 : 0.f;
        *reinterpret_cast<float2*>(&H[(size_t)warp * 64 + lane * 2]) = make_float2(v0, v1);

        float part = v0 * aW[lane * 2] + v1 * aW[lane * 2 + 1];
#pragma unroll
        for (int o = 16; o; o >>= 1) part += __shfl_xor_sync(0xFFFFFFFFu, part, o);
        a = part + ab[0];
        if (lane == 0) g_a[warp] = a;
    }

    __shared__ float sm[8];
    __shared__ float bmax_s;
    if (lane == 0) sm[threadIdx.x >> 5] = a;
    __syncthreads();
    if (threadIdx.x == 0) {
        float m = sm[0];
#pragma unroll
        for (int i = 1; i < 8; i++) m = fmaxf(m, sm[i]);
        bmax_s = m;
    }
    __syncthreads();
    float bmax = bmax_s;
    float es = (lane == 0 && warp < n) ? expf(a - bmax) : 0.f;
    if (lane == 0) sm[threadIdx.x >> 5] = es;
    __syncthreads();
    if (threadIdx.x == 0) {
        float s = sm[0];
#pragma unroll
        for (int i = 1; i < 8; i++) s += sm[i];
        g_red[blockIdx.x * 2] = bmax;
        g_red[blockIdx.x * 2 + 1] = s;
    }
}

// ---------------- softmax combine + final ----------------
__global__ void combine_kernel(int nb) {
    __shared__ float sm[1024];
    int t = threadIdx.x;
    float m = -INFINITY;
    for (int i = t; i < nb; i += 1024) m = fmaxf(m, g_red[i * 2]);
    sm[t] = m;
    __syncthreads();
    for (int o = 512; o; o >>= 1) {
        if (t < o) sm[t] = fmaxf(sm[t], sm[t + o]);
        __syncthreads();
    }
    float gmax = sm[0];
    __syncthreads();
    float s = 0.f;
    for (int i = t; i < nb; i += 1024) s += g_red[i * 2 + 1] * expf(g_red[i * 2] - gmax);
    sm[t] = s;
    __syncthreads();
    for (int o = 512; o; o >>= 1) {
        if (t < o) sm[t] += sm[t + o];
        __syncthreads();
    }
    if (t == 0) { g_scalar[0] = gmax; g_scalar[1] = sm[0]; }
}

__global__ void final_kernel(const float* __restrict__ H,
                             const float* __restrict__ fW,
                             const float* __restrict__ fb,
                             float* __restrict__ out, int n) {
    int gw = (blockIdx.x * blockDim.x + threadIdx.x) >> 5;
    int lane = threadIdx.x & 31;
    if (gw >= n) return;
    float v = H[(size_t)gw * 64 + lane] * fW[lane] +
              H[(size_t)gw * 64 + lane + 32] * fW[lane + 32];
#pragma unroll
    for (int o = 16; o; o >>= 1) v += __shfl_xor_sync(0xFFFFFFFFu, v, o);
    if (lane == 0) {
        float attn = expf(g_a[gw] - g_scalar[0]) / g_scalar[1];
        float z = attn * v + fb[0];
        out[gw] = 1.f / (1.f + expf(-z));
        out[n + gw] = attn;
    }
}

// ---------------- launch ----------------
extern "C" void kernel_launch(void* const* d_in, const int* in_sizes, int n_in,
                              void* d_out, int out_size) {
    const float* x   = (const float*)d_in[0];
    const int*   ei  = (const int*)d_in[1];
    const float* W1  = (const float*)d_in[2];
    const float* b1  = (const float*)d_in[3];
    const float* W2  = (const float*)d_in[4];
    const float* b2  = (const float*)d_in[5];
    const float* W3  = (const float*)d_in[6];
    const float* b3  = (const float*)d_in[7];
    const float* aW  = (const float*)d_in[8];
    const float* ab  = (const float*)d_in[9];
    const float* fW  = (const float*)d_in[10];
    const float* fb  = (const float*)d_in[11];
    float* out = (float*)d_out;

    int N = in_sizes[0] / 128;
    int E = in_sizes[1] / 2;
    const int* src = ei;
    const int* dst = ei + E;

    __nv_bfloat16 *tb, *hb, *w1t, *w2t, *w3t;
    float* h3;
    int* deg_ptr;
    cudaGetSymbolAddress((void**)&tb, g_tb);
    cudaGetSymbolAddress((void**)&hb, g_hb);
    cudaGetSymbolAddress((void**)&h3, g_h);
    cudaGetSymbolAddress((void**)&deg_ptr, g_deg);
    cudaGetSymbolAddress((void**)&w1t, g_w1t);
    cudaGetSymbolAddress((void**)&w2t, g_w2t);
    cudaGetSymbolAddress((void**)&w3t, g_w3t);

    const int SM128 = 128 * LDW * 2;
    const int SM64  = 64 * LDW * 2;
    cudaFuncSetAttribute((const void*)mma_gemm_kernel<128, float>,
                         cudaFuncAttributeMaxDynamicSharedMemorySize, SM128);
    cudaFuncSetAttribute((const void*)mma_gemm_kernel<128, __nv_bfloat16>,
                         cudaFuncAttributeMaxDynamicSharedMemorySize, SM128);
    cudaFuncSetAttribute((const void*)mma_gemm_kernel<64, __nv_bfloat16>,
                         cudaFuncAttributeMaxDynamicSharedMemorySize, SM64);

    cudaMemsetAsync(deg_ptr, 0, (size_t)N * sizeof(int));
    prep_count_kernel<<<PREP_B + (E + 255) / 256, 256>>>(W1, W2, W3, dst, E);
    int nb = (N + SCAN_B - 1) / SCAN_B;
    scan1_kernel<<<nb, 256>>>(N, E);
    scan3_kernel<<<nb, 256>>>(N);
    fill_kernel<<<(E + 255) / 256, 256>>>(src, dst, E);

    int warpGrid = (N * 32 + 255) / 256;
    int mmaGrid = (N + 127) / 128;

    mma_gemm_kernel<128, float><<<mmaGrid, 256, SM128>>>(x, w1t, tb, N);
    agg128_kernel<<<warpGrid, 256>>>(tb, b1, hb, N);
    mma_gemm_kernel<128, __nv_bfloat16><<<mmaGrid, 256, SM128>>>(hb, w2t, tb, N);
    agg128_kernel<<<warpGrid, 256>>>(tb, b2, hb, N);
    mma_gemm_kernel<64, __nv_bfloat16><<<mmaGrid, 256, SM64>>>(hb, w3t, tb, N);
    agg3_attn_kernel<<<warpGrid, 256>>>(tb, b3, aW, ab, h3, N);

    combine_kernel<<<1, 1024>>>(warpGrid);
    final_kernel<<<warpGrid, 256>>>(h3, fW, fb, out, N);
}

// round 10
// speedup vs baseline: 1.1110x; 1.0455x over previous
#include <cuda_runtime.h>
#include <cuda_bf16.h>
#include <math.h>
#include <stdint.h>

// Problem constants: N=50000, E=800000, dims 128/128/128/64.
#define MAXN 50000
#define MAXE 800000
#define LDW 136     // padded bf16 k-stride for transposed weights
#define SCAN_B 2048

// ---------------- scratch (device globals) ----------------
__device__ __nv_bfloat16 g_tb[MAXN * 128];  // GEMM output (bf16)
__device__ __nv_bfloat16 g_hb[MAXN * 128];  // layer activations (bf16)
__device__ float g_v[MAXN];                 // per-node fc dot products
__device__ float g_dis[MAXN];               // rsqrt(deg)
__device__ int   g_deg[MAXN];               // in-degree counts
__device__ int   g_off[MAXN + 1];           // CSR offsets
__device__ int   g_rank[MAXE];              // per-edge rank within dst bucket
__device__ int   g_csrc[MAXE];              // CSR src indices (grouped by dst)
__device__ float g_a[MAXN];                 // attention logits
__device__ float g_red[16384];              // block partials
__device__ float g_scalar[2];               // [0]=gmax, [1]=gsum
__device__ int   g_bsum[64];                // scan block sums
__device__ int   g_ticket;                  // agg3 completion ticket (self-resetting)
__device__ __nv_bfloat16 g_w1t[128 * LDW];
__device__ __nv_bfloat16 g_w2t[128 * LDW];
__device__ __nv_bfloat16 g_w3t[64 * LDW];

// ---------------- helpers ----------------
__device__ __forceinline__ void mma16816(float* d, uint32_t a0, uint32_t a1,
                                         uint32_t a2, uint32_t a3,
                                         uint32_t b0, uint32_t b1) {
    asm volatile(
        "mma.sync.aligned.m16n8k16.row.col.f32.bf16.bf16.f32 "
        "{%0,%1,%2,%3}, {%4,%5,%6,%7}, {%8,%9}, {%0,%1,%2,%3};"
        : "+f"(d[0]), "+f"(d[1]), "+f"(d[2]), "+f"(d[3])
        : "r"(a0), "r"(a1), "r"(a2), "r"(a3), "r"(b0), "r"(b1));
}

__device__ __forceinline__ float2 bf2f(uint32_t u) {
    return __bfloat1622float2(*reinterpret_cast<__nv_bfloat162*>(&u));
}

// ---------------- weight prep (own kernel; main stream) ----------------
__global__ void prep_w_kernel(const float* __restrict__ W1, const float* __restrict__ W2,
                              const float* __restrict__ W3) {
    int i = blockIdx.x * 256 + threadIdx.x;
    if (i < 128 * 128) {
        int k = i >> 7, nn = i & 127;
        g_w1t[nn * LDW + k] = __float2bfloat16(W1[i]);
        g_w2t[nn * LDW + k] = __float2bfloat16(W2[i]);
    }
    if (i < 128 * 64) {
        int k = i >> 6, nn = i & 63;
        g_w3t[nn * LDW + k] = __float2bfloat16(W3[i]);
    }
}

// ---------------- degree count (CSR stream) ----------------
__global__ void count_kernel(const int* __restrict__ dst, int e) {
    int i = blockIdx.x * blockDim.x + threadIdx.x;
    if (i < e) g_rank[i] = atomicAdd(&g_deg[dst[i]], 1);
}

// ---------------- scan phase 1: per-block sums ----------------
__global__ void scan1_kernel(int n, int e) {
    __shared__ int sm[256];
    int base = blockIdx.x * SCAN_B + threadIdx.x * 8;
    int s = 0;
#pragma unroll
    for (int i = 0; i < 8; i++) {
        int idx = base + i;
        if (idx < n) s += g_deg[idx];
    }
    sm[threadIdx.x] = s;
    __syncthreads();
    for (int o = 128; o; o >>= 1) {
        if (threadIdx.x < o) sm[threadIdx.x] += sm[threadIdx.x + o];
        __syncthreads();
    }
    if (threadIdx.x == 0) {
        g_bsum[blockIdx.x] = sm[0];
        if (blockIdx.x == 0) g_off[n] = e;
    }
}

// ---------------- scan phase 2: block-local scan + inline block prefix ----------------
__global__ void scan3_kernel(int n) {
    __shared__ int sm[256];
    __shared__ int boff_s;
    int t = threadIdx.x;
    if (t < 32) {
        int v = 0;
        for (int i = t; i < (int)blockIdx.x; i += 32) v += g_bsum[i];
#pragma unroll
        for (int o = 16; o; o >>= 1) v += __shfl_xor_sync(0xFFFFFFFFu, v, o);
        if (t == 0) boff_s = v;
    }
    int base = blockIdx.x * SCAN_B + t * 8;
    int loc[8];
    int s = 0;
#pragma unroll
    for (int i = 0; i < 8; i++) {
        int idx = base + i;
        loc[i] = (idx < n) ? g_deg[idx] : 0;
        s += loc[i];
    }
    sm[t] = s;
    __syncthreads();
    for (int off = 1; off < 256; off <<= 1) {
        int v = (t >= off) ? sm[t - off] : 0;
        __syncthreads();
        sm[t] += v;
        __syncthreads();
    }
    int prefix = boff_s + sm[t] - s;
#pragma unroll
    for (int i = 0; i < 8; i++) {
        int idx = base + i;
        if (idx < n) {
            g_off[idx] = prefix;
            prefix += loc[i];
            g_dis[idx] = rsqrtf((float)loc[i] + 1.0f);
        }
    }
}

__global__ void fill_kernel(const int* __restrict__ src, const int* __restrict__ dst, int e) {
    int i = blockIdx.x * blockDim.x + threadIdx.x;
    if (i >= e) return;
    g_csrc[g_off[dst[i]] + g_rank[i]] = src[i];
}

// ---------------- bf16 mma GEMM: T[n,OUT](bf16) = A[n,128] @ W[128,OUT] ----------------
template <int OUT, typename AF>
__global__ __launch_bounds__(256) void mma_gemm_kernel(const AF* __restrict__ A,
                                                       const __nv_bfloat16* __restrict__ Wt,
                                                       __nv_bfloat16* __restrict__ T, int n) {
    extern __shared__ __nv_bfloat16 sw[];  // [OUT][LDW]
    int t = threadIdx.x;
    constexpr int NU4 = OUT * LDW / 8;
    for (int i = t; i < NU4; i += 256)
        reinterpret_cast<uint4*>(sw)[i] = reinterpret_cast<const uint4*>(Wt)[i];
    __syncthreads();

    int warp = t >> 5, lane = t & 31;
    int g = lane >> 2, tg = lane & 3;
    int row0 = blockIdx.x * 128 + warp * 16 + g;
    int row1 = row0 + 8;
    bool v0 = row0 < n, v1 = row1 < n;

    constexpr int NT = OUT / 8;
    float acc[NT][4];
#pragma unroll
    for (int i = 0; i < NT; i++)
#pragma unroll
        for (int j = 0; j < 4; j++) acc[i][j] = 0.f;

    const AF* A0 = A + (size_t)row0 * 128;
    const AF* A1 = A + (size_t)row1 * 128;

#pragma unroll
    for (int ks = 0; ks < 8; ks++) {
        int k0 = ks * 16 + tg * 2;
        uint32_t a0, a1, a2, a3;
        if (sizeof(AF) == 4) {
            const float* F0 = (const float*)A0;
            const float* F1 = (const float*)A1;
            float2 z = make_float2(0.f, 0.f);
            float2 x0 = v0 ? *reinterpret_cast<const float2*>(F0 + k0) : z;
            float2 x1 = v1 ? *reinterpret_cast<const float2*>(F1 + k0) : z;
            float2 x2 = v0 ? *reinterpret_cast<const float2*>(F0 + k0 + 8) : z;
            float2 x3 = v1 ? *reinterpret_cast<const float2*>(F1 + k0 + 8) : z;
            __nv_bfloat162 h0 = __float22bfloat162_rn(x0);
            __nv_bfloat162 h1 = __float22bfloat162_rn(x1);
            __nv_bfloat162 h2 = __float22bfloat162_rn(x2);
            __nv_bfloat162 h3 = __float22bfloat162_rn(x3);
            a0 = *reinterpret_cast<uint32_t*>(&h0);
            a1 = *reinterpret_cast<uint32_t*>(&h1);
            a2 = *reinterpret_cast<uint32_t*>(&h2);
            a3 = *reinterpret_cast<uint32_t*>(&h3);
        } else {
            const __nv_bfloat16* B0 = (const __nv_bfloat16*)A0;
            const __nv_bfloat16* B1 = (const __nv_bfloat16*)A1;
            a0 = v0 ? *reinterpret_cast<const uint32_t*>(B0 + k0) : 0u;
            a1 = v1 ? *reinterpret_cast<const uint32_t*>(B1 + k0) : 0u;
            a2 = v0 ? *reinterpret_cast<const uint32_t*>(B0 + k0 + 8) : 0u;
            a3 = v1 ? *reinterpret_cast<const uint32_t*>(B1 + k0 + 8) : 0u;
        }

        const __nv_bfloat16* wh = sw + g * LDW + ks * 16 + tg * 2;
#pragma unroll
        for (int nt = 0; nt < NT; nt++) {
            uint32_t b0 = *reinterpret_cast<const uint32_t*>(wh + nt * 8 * LDW);
            uint32_t b1 = *reinterpret_cast<const uint32_t*>(wh + nt * 8 * LDW + 8);
            mma16816(acc[nt], a0, a1, a2, a3, b0, b1);
        }
    }

#pragma unroll
    for (int nt = 0; nt < NT; nt++) {
        int col = nt * 8 + tg * 2;
        if (v0) {
            __nv_bfloat162 o = __float22bfloat162_rn(make_float2(acc[nt][0], acc[nt][1]));
            *reinterpret_cast<__nv_bfloat162*>(&T[(size_t)row0 * OUT + col]) = o;
        }
        if (v1) {
            __nv_bfloat162 o = __float22bfloat162_rn(make_float2(acc[nt][2], acc[nt][3]));
            *reinterpret_cast<__nv_bfloat162*>(&T[(size_t)row1 * OUT + col]) = o;
        }
    }
}

// ---------------- aggregation layers 1,2 (bf16->bf16, OUT=128, unroll x8) ----------------
__global__ __launch_bounds__(256) void agg128_kernel(const __nv_bfloat16* __restrict__ T,
                                                     const float* __restrict__ bias,
                                                     __nv_bfloat16* __restrict__ H, int n) {
    int warp = (blockIdx.x * blockDim.x + threadIdx.x) >> 5;
    int lane = threadIdx.x & 31;
    if (warp >= n) return;

    float dn = g_dis[warp];
    float w0 = dn * dn;
    float acc[4];
    {
        uint2 u = *reinterpret_cast<const uint2*>(&T[(size_t)warp * 128 + lane * 4]);
        float2 f0 = bf2f(u.x), f1 = bf2f(u.y);
        acc[0] = f0.x * w0; acc[1] = f0.y * w0;
        acc[2] = f1.x * w0; acc[3] = f1.y * w0;
    }

    int p0 = g_off[warp];
    int cnt = g_off[warp + 1] - p0;
    int sv = (lane < cnt) ? g_csrc[p0 + lane] : 0;
    int j = 0;
    for (; j + 8 <= cnt; j += 8) {
        if ((j & 31) == 0 && j)
            sv = (j + lane < cnt) ? g_csrc[p0 + j + lane] : 0;
        int jb = j & 31;
        int s[8];
#pragma unroll
        for (int q = 0; q < 8; q++) s[q] = __shfl_sync(0xFFFFFFFFu, sv, jb + q);
        float w[8];
#pragma unroll
        for (int q = 0; q < 8; q++) w[q] = g_dis[s[q]] * dn;
        uint2 u[8];
#pragma unroll
        for (int q = 0; q < 8; q++)
            u[q] = *reinterpret_cast<const uint2*>(&T[(size_t)s[q] * 128 + lane * 4]);
#pragma unroll
        for (int q = 0; q < 8; q++) {
            float2 f0 = bf2f(u[q].x), f1 = bf2f(u[q].y);
            acc[0] = fmaf(f0.x, w[q], acc[0]); acc[1] = fmaf(f0.y, w[q], acc[1]);
            acc[2] = fmaf(f1.x, w[q], acc[2]); acc[3] = fmaf(f1.y, w[q], acc[3]);
        }
    }
    for (; j < cnt; j++) {
        if ((j & 31) == 0 && j)
            sv = (j + lane < cnt) ? g_csrc[p0 + j + lane] : 0;
        int s = __shfl_sync(0xFFFFFFFFu, sv, j & 31);
        float w = g_dis[s] * dn;
        uint2 u = *reinterpret_cast<const uint2*>(&T[(size_t)s * 128 + lane * 4]);
        float2 f0 = bf2f(u.x), f1 = bf2f(u.y);
        acc[0] = fmaf(f0.x, w, acc[0]); acc[1] = fmaf(f0.y, w, acc[1]);
        acc[2] = fmaf(f1.x, w, acc[2]); acc[3] = fmaf(f1.y, w, acc[3]);
    }

#pragma unroll
    for (int q = 0; q < 4; q++) {
        float v = acc[q] + bias[lane * 4 + q];
        acc[q] = v > 0.f ? v : 0.f;
    }
    __nv_bfloat162 o0 = __float22bfloat162_rn(make_float2(acc[0], acc[1]));
    __nv_bfloat162 o1 = __float22bfloat162_rn(make_float2(acc[2], acc[3]));
    uint2 u;
    u.x = *reinterpret_cast<uint32_t*>(&o0);
    u.y = *reinterpret_cast<uint32_t*>(&o1);
    *reinterpret_cast<uint2*>(&H[(size_t)warp * 128 + lane * 4]) = u;
}

// ---------------- fused layer-3 agg + attention + fc dots + ticket combine ----------------
__global__ __launch_bounds__(256) void agg3_attn_kernel(const __nv_bfloat16* __restrict__ T,
                                                        const float* __restrict__ bias,
                                                        const float* __restrict__ aW,
                                                        const float* __restrict__ ab,
                                                        const float* __restrict__ fW, int n) {
    int warp = (blockIdx.x * blockDim.x + threadIdx.x) >> 5;
    int lane = threadIdx.x & 31;
    float a = -INFINITY;

    if (warp < n) {
        float dn = g_dis[warp];
        float w0 = dn * dn;
        float acc0, acc1;
        {
            uint32_t u = *reinterpret_cast<const uint32_t*>(&T[(size_t)warp * 64 + lane * 2]);
            float2 f = bf2f(u);
            acc0 = f.x * w0; acc1 = f.y * w0;
        }
        int p0 = g_off[warp];
        int cnt = g_off[warp + 1] - p0;
        int sv = (lane < cnt) ? g_csrc[p0 + lane] : 0;
        int j = 0;
        for (; j + 8 <= cnt; j += 8) {
            if ((j & 31) == 0 && j)
                sv = (j + lane < cnt) ? g_csrc[p0 + j + lane] : 0;
            int jb = j & 31;
            int s[8];
#pragma unroll
            for (int q = 0; q < 8; q++) s[q] = __shfl_sync(0xFFFFFFFFu, sv, jb + q);
            float w[8];
#pragma unroll
            for (int q = 0; q < 8; q++) w[q] = g_dis[s[q]] * dn;
            uint32_t u[8];
#pragma unroll
            for (int q = 0; q < 8; q++)
                u[q] = *reinterpret_cast<const uint32_t*>(&T[(size_t)s[q] * 64 + lane * 2]);
#pragma unroll
            for (int q = 0; q < 8; q++) {
                float2 f = bf2f(u[q]);
                acc0 = fmaf(f.x, w[q], acc0); acc1 = fmaf(f.y, w[q], acc1);
            }
        }
        for (; j < cnt; j++) {
            if ((j & 31) == 0 && j)
                sv = (j + lane < cnt) ? g_csrc[p0 + j + lane] : 0;
            int s = __shfl_sync(0xFFFFFFFFu, sv, j & 31);
            float w = g_dis[s] * dn;
            uint32_t u = *reinterpret_cast<const uint32_t*>(&T[(size_t)s * 64 + lane * 2]);
            float2 f = bf2f(u);
            acc0 = fmaf(f.x, w, acc0); acc1 = fmaf(f.y, w, acc1);
        }

        float v0 = acc0 + bias[lane * 2];
        float v1 = acc1 + bias[lane * 2 + 1];
        v0 = v0 > 0.f ? v0 : 0.f;
        v1 = v1 > 0.f ? v1 : 0.f;

        // attention + fc dots straight from registers (no H round-trip)
        float pa = v0 * aW[lane * 2] + v1 * aW[lane * 2 + 1];
        float pv = v0 * fW[lane * 2] + v1 * fW[lane * 2 + 1];
#pragma unroll
        for (int o = 16; o; o >>= 1) {
            pa += __shfl_xor_sync(0xFFFFFFFFu, pa, o);
            pv += __shfl_xor_sync(0xFFFFFFFFu, pv, o);
        }
        a = pa + ab[0];
        if (lane == 0) { g_a[warp] = a; g_v[warp] = pv; }
    }

    // block partials
    __shared__ float sm[8];
    __shared__ float bmax_s;
    if (lane == 0) sm[threadIdx.x >> 5] = a;
    __syncthreads();
    if (threadIdx.x == 0) {
        float m = sm[0];
#pragma unroll
        for (int i = 1; i < 8; i++) m = fmaxf(m, sm[i]);
        bmax_s = m;
    }
    __syncthreads();
    float bmax = bmax_s;
    float es = (lane == 0 && warp < n) ? expf(a - bmax) : 0.f;
    if (lane == 0) sm[threadIdx.x >> 5] = es;
    __syncthreads();
    if (threadIdx.x == 0) {
        float s = sm[0];
#pragma unroll
        for (int i = 1; i < 8; i++) s += sm[i];
        g_red[blockIdx.x * 2] = bmax;
        g_red[blockIdx.x * 2 + 1] = s;
    }

    // ticket: last block performs the global combine
    __shared__ int isLast;
    if (threadIdx.x == 0) {
        __threadfence();
        int tk = atomicAdd(&g_ticket, 1);
        isLast = (tk == (int)gridDim.x - 1);
    }
    __syncthreads();
    if (isLast) {
        __shared__ float red[256];
        int t = threadIdx.x;
        int nb = gridDim.x;
        float m = -INFINITY;
        for (int i = t; i < nb; i += 256) m = fmaxf(m, g_red[i * 2]);
        red[t] = m;
        __syncthreads();
        for (int o = 128; o; o >>= 1) {
            if (t < o) red[t] = fmaxf(red[t], red[t + o]);
            __syncthreads();
        }
        float gmax = red[0];
        __syncthreads();
        float s = 0.f;
        for (int i = t; i < nb; i += 256) s += g_red[i * 2 + 1] * expf(g_red[i * 2] - gmax);
        red[t] = s;
        __syncthreads();
        for (int o = 128; o; o >>= 1) {
            if (t < o) red[t] += red[t + o];
            __syncthreads();
        }
        if (t == 0) {
            g_scalar[0] = gmax;
            g_scalar[1] = red[0];
            g_ticket = 0;  // self-reset for next replay
        }
    }
}

// ---------------- final: elementwise ----------------
__global__ void final_kernel(const float* __restrict__ fb, float* __restrict__ out, int n) {
    int i = blockIdx.x * blockDim.x + threadIdx.x;
    if (i >= n) return;
    float attn = expf(g_a[i] - g_scalar[0]) / g_scalar[1];
    float z = attn * g_v[i] + fb[0];
    out[i] = 1.f / (1.f + expf(-z));
    out[n + i] = attn;
}

// ---------------- launch ----------------
extern "C" void kernel_launch(void* const* d_in, const int* in_sizes, int n_in,
                              void* d_out, int out_size) {
    const float* x   = (const float*)d_in[0];
    const int*   ei  = (const int*)d_in[1];
    const float* W1  = (const float*)d_in[2];
    const float* b1  = (const float*)d_in[3];
    const float* W2  = (const float*)d_in[4];
    const float* b2  = (const float*)d_in[5];
    const float* W3  = (const float*)d_in[6];
    const float* b3  = (const float*)d_in[7];
    const float* aW  = (const float*)d_in[8];
    const float* ab  = (const float*)d_in[9];
    const float* fW  = (const float*)d_in[10];
    const float* fb  = (const float*)d_in[11];
    float* out = (float*)d_out;

    int N = in_sizes[0] / 128;
    int E = in_sizes[1] / 2;
    const int* src = ei;
    const int* dst = ei + E;

    __nv_bfloat16 *tb, *hb, *w1t, *w2t, *w3t;
    int* deg_ptr;
    cudaGetSymbolAddress((void**)&tb, g_tb);
    cudaGetSymbolAddress((void**)&hb, g_hb);
    cudaGetSymbolAddress((void**)&deg_ptr, g_deg);
    cudaGetSymbolAddress((void**)&w1t, g_w1t);
    cudaGetSymbolAddress((void**)&w2t, g_w2t);
    cudaGetSymbolAddress((void**)&w3t, g_w3t);

    const int SM128 = 128 * LDW * 2;
    const int SM64  = 64 * LDW * 2;
    cudaFuncSetAttribute((const void*)mma_gemm_kernel<128, float>,
                         cudaFuncAttributeMaxDynamicSharedMemorySize, SM128);
    cudaFuncSetAttribute((const void*)mma_gemm_kernel<128, __nv_bfloat16>,
                         cudaFuncAttributeMaxDynamicSharedMemorySize, SM128);
    cudaFuncSetAttribute((const void*)mma_gemm_kernel<64, __nv_bfloat16>,
                         cudaFuncAttributeMaxDynamicSharedMemorySize, SM64);

    // fork a side stream for the CSR build (independent of GEMM1 chain).
    // created per-call and not destroyed (destroying a forked stream mid-capture
    // invalidates the capture); host-side only, zero replay cost.
    cudaStream_t s1;
    cudaStreamCreateWithFlags(&s1, cudaStreamNonBlocking);
    cudaEvent_t eFork, eJoin;
    cudaEventCreateWithFlags(&eFork, cudaEventDisableTiming);
    cudaEventCreateWithFlags(&eJoin, cudaEventDisableTiming);

    cudaEventRecord(eFork, 0);
    cudaStreamWaitEvent(s1, eFork, 0);

    // --- CSR branch (s1) ---
    cudaMemsetAsync(deg_ptr, 0, (size_t)N * sizeof(int), s1);
    count_kernel<<<(E + 255) / 256, 256, 0, s1>>>(dst, E);
    int nb = (N + SCAN_B - 1) / SCAN_B;
    scan1_kernel<<<nb, 256, 0, s1>>>(N, E);
    scan3_kernel<<<nb, 256, 0, s1>>>(N);
    fill_kernel<<<(E + 255) / 256, 256, 0, s1>>>(src, dst, E);
    cudaEventRecord(eJoin, s1);

    // --- main branch (stream 0): weights + GEMM1 ---
    int warpGrid = (N * 32 + 255) / 256;
    int mmaGrid = (N + 127) / 128;

    prep_w_kernel<<<64, 256>>>(W1, W2, W3);
    mma_gemm_kernel<128, float><<<mmaGrid, 256, SM128>>>(x, w1t, tb, N);

    // join: aggregation needs the CSR
    cudaStreamWaitEvent(0, eJoin, 0);

    agg128_kernel<<<warpGrid, 256>>>(tb, b1, hb, N);
    mma_gemm_kernel<128, __nv_bfloat16><<<mmaGrid, 256, SM128>>>(hb, w2t, tb, N);
    agg128_kernel<<<warpGrid, 256>>>(tb, b2, hb, N);
    mma_gemm_kernel<64, __nv_bfloat16><<<mmaGrid, 256, SM64>>>(hb, w3t, tb, N);
    agg3_attn_kernel<<<warpGrid, 256>>>(tb, b3, aW, ab, fW, N);
    final_kernel<<<(N + 255) / 256, 256>>>(fb, out, N);
}